// round 10
// baseline (speedup 1.0000x reference)
#include <cuda_runtime.h>
#include <math_constants.h>

// out = minmax_normalize( bicubic_up2x( LL[:, 0:8] ) )
// All other iqwt terms carry sum(gh)=sum(fl)=sum(fh)=0 (f32 residue < 3e-7);
// the surviving sg^2 scalar cancels in the min-max normalization.
//
// Single persistent kernel, one wave (512 blocks, all resident):
//   phase 1: fill 36-row slab (4 tiles) -> min/max -> atomics -> grid barrier
//   phase 2: recompute from the SAME smem slab -> normalize -> stores
// Input is read from DRAM exactly once; no second launch, no second fill.

#define THREADS 256
#define NT      4                     // tiles per block
#define TILE_J  8                     // input rows per tile -> 16 output rows
#define BUF_ROWS (NT * TILE_J + 4)    // 36 rows incl. shared halo
#define SMEM_W  264                   // 4 pad | 256 | 4 pad (16B-aligned rows)
#define N_IN    256
#define N_OUT   512
#define N_IMG   64
#define NBLK    (N_IMG * 32 / NT)     // 512 blocks, single wave

// bicubic a=-0.75, src = 0.5*i - 0.25
#define WE0 (-0.03515625f)
#define WE1 ( 0.26171875f)
#define WE2 ( 0.87890625f)
#define WE3 (-0.10546875f)
#define WO0 (-0.10546875f)
#define WO1 ( 0.87890625f)
#define WO2 ( 0.26171875f)
#define WO3 (-0.03515625f)

__device__ unsigned int g_red[2];    // [0]=min(enc(v)), [1]=min(enc(-v))
__device__ unsigned int g_count;     // grid-barrier arrivals

__device__ __forceinline__ unsigned int encf(float f) {
    unsigned int u = __float_as_uint(f);
    return (u & 0x80000000u) ? ~u : (u | 0x80000000u);
}
__device__ __forceinline__ float decf(unsigned int e) {
    unsigned int u = (e & 0x80000000u) ? (e ^ 0x80000000u) : ~u ^ 0u;
    u = (e & 0x80000000u) ? (e ^ 0x80000000u) : ~e;
    return __uint_as_float(u);
}

__device__ __forceinline__ void hpass_tile(const float (*s)[SMEM_W],
                                           int rowbase, int k, float hb[8][4]) {
#pragma unroll
    for (int r = 0; r < 8; r++) {
        const float* rp = &s[rowbase + r][2 * k + 2];
        const float2 z01 = *reinterpret_cast<const float2*>(rp);
        const float2 z23 = *reinterpret_cast<const float2*>(rp + 2);
        const float2 z45 = *reinterpret_cast<const float2*>(rp + 4);
        const float z0 = z01.x, z1 = z01.y, z2 = z23.x;
        const float z3 = z23.y, z4 = z45.x, z5 = z45.y;
        hb[r][0] = WE0 * z0 + WE1 * z1 + WE2 * z2 + WE3 * z3;
        hb[r][1] = WO0 * z1 + WO1 * z2 + WO2 * z3 + WO3 * z4;
        hb[r][2] = WE0 * z1 + WE1 * z2 + WE2 * z3 + WE3 * z4;
        hb[r][3] = WO0 * z2 + WO1 * z3 + WO2 * z4 + WO3 * z5;
    }
}

__device__ __forceinline__ void vrow(const float hb[8][4], int a, float o[4]) {
    const int ra = a >> 1;
    if ((a & 1) == 0) {
#pragma unroll
        for (int c = 0; c < 4; c++)
            o[c] = WE0 * hb[ra][c] + WE1 * hb[ra + 1][c]
                 + WE2 * hb[ra + 2][c] + WE3 * hb[ra + 3][c];
    } else {
#pragma unroll
        for (int c = 0; c < 4; c++)
            o[c] = WO0 * hb[ra + 1][c] + WO1 * hb[ra + 2][c]
                 + WO2 * hb[ra + 3][c] + WO3 * hb[ra + 4][c];
    }
}

__global__ __launch_bounds__(THREADS, 4)
void qwt_fused_kernel(const float* __restrict__ LL, float* __restrict__ out) {
    __shared__ __align__(16) float s[BUF_ROWS][SMEM_W];
    __shared__ float wmin[THREADS / 32], wmax[THREADS / 32];

    const int t     = threadIdx.x;
    const int tile0 = blockIdx.x * NT;       // 4 tiles within one image
    const int img   = tile0 >> 5;            // 0..63
    const int b     = img >> 3;
    const int ch    = img & 7;               // lglg = LL channels 0..7
    const float* __restrict__ src = LL + (size_t)(b * 32 + ch) * (N_IN * N_IN);
    const int jbase = (tile0 & 31) * TILE_J; // first input row - 2 = slab row 0

    // ---- Fill 36x264 slab: 2304 float4 chunks, 9/thread, coalesced. -------
#pragma unroll
    for (int i = 0; i < 9; i++) {
        const int f  = t + i * THREADS;      // 0..2303
        const int rr = f >> 6;               // 0..35
        const int qc = f & 63;
        const int gr = min(max(jbase - 2 + rr, 0), N_IN - 1);
        *reinterpret_cast<float4*>(&s[rr][4 * qc + 4]) =
            *reinterpret_cast<const float4*>(src + gr * N_IN + 4 * qc);
    }
    if (t < BUF_ROWS) {
        const int gr = min(max(jbase - 2 + t, 0), N_IN - 1);
        const float v = src[gr * N_IN];
        s[t][2] = v; s[t][3] = v;
    } else if (t >= 128 && t < 128 + BUF_ROWS) {
        const int rr = t - 128;
        const int gr = min(max(jbase - 2 + rr, 0), N_IN - 1);
        const float v = src[gr * N_IN + (N_IN - 1)];
        s[rr][260] = v; s[rr][261] = v;
    }
    __syncthreads();

    const int k = t & 127;                   // out cols 4k..4k+3
    const int g = t >> 7;                    // per-tile out rows 8g..8g+7

    // ---- Phase 1: min/max over all 4 tiles. -------------------------------
    float lmin =  CUDART_INF_F;
    float lmax = -CUDART_INF_F;
#pragma unroll
    for (int tt = 0; tt < NT; tt++) {
        float hb[8][4];
        hpass_tile(s, 8 * tt + 4 * g, k, hb);
#pragma unroll
        for (int a = 0; a < 8; a++) {
            float o[4];
            vrow(hb, a, o);
            lmin = fminf(lmin, fminf(fminf(o[0], o[1]), fminf(o[2], o[3])));
            lmax = fmaxf(lmax, fmaxf(fmaxf(o[0], o[1]), fmaxf(o[2], o[3])));
        }
    }
#pragma unroll
    for (int off = 16; off > 0; off >>= 1) {
        lmin = fminf(lmin, __shfl_xor_sync(0xFFFFFFFFu, lmin, off));
        lmax = fmaxf(lmax, __shfl_xor_sync(0xFFFFFFFFu, lmax, off));
    }
    const int w = t >> 5, l = t & 31;
    if (l == 0) { wmin[w] = lmin; wmax[w] = lmax; }
    __syncthreads();
    if (t == 0) {
        float m = wmin[0], M = wmax[0];
#pragma unroll
        for (int i = 1; i < THREADS / 32; i++) {
            m = fminf(m, wmin[i]);
            M = fmaxf(M, wmax[i]);
        }
        atomicMin(&g_red[0], encf(m));
        atomicMin(&g_red[1], encf(-M));
        __threadfence();
        atomicAdd(&g_count, 1u);             // arrive
    }

    // Overlap part of tile 0's phase-2 work with the barrier wait.
    float hb0[8][4];
    hpass_tile(s, 4 * g, k, hb0);

    if (t == 0) {                            // spin until all 512 arrived
        while (atomicAdd(&g_count, 0u) < NBLK) __nanosleep(64);
    }
    __syncthreads();
    __threadfence();

    const float mn =  decf(atomicAdd(&g_red[0], 0u));
    const float mx = -decf(atomicAdd(&g_red[1], 0u));
    const float scale = 1.0f / (mx - mn);
    const float bias  = -mn * scale;

    // ---- Phase 2: recompute from resident smem, normalize, store. ---------
    const size_t obase = (size_t)img * (N_OUT * N_OUT) + 4 * k;
#pragma unroll
    for (int tt = 0; tt < NT; tt++) {
        float hb[8][4];
        if (tt == 0) {
#pragma unroll
            for (int r = 0; r < 8; r++)
#pragma unroll
                for (int c = 0; c < 4; c++) hb[r][c] = hb0[r][c];
        } else {
            hpass_tile(s, 8 * tt + 4 * g, k, hb);
        }
        const int rbase = ((tile0 + tt) & 31) * 16 + 8 * g;
#pragma unroll
        for (int a = 0; a < 8; a++) {
            float o[4];
            vrow(hb, a, o);
            float4 v;
            v.x = fmaf(o[0], scale, bias); v.y = fmaf(o[1], scale, bias);
            v.z = fmaf(o[2], scale, bias); v.w = fmaf(o[3], scale, bias);
            *reinterpret_cast<float4*>(out + obase + (size_t)(rbase + a) * N_OUT) = v;
        }
    }
}

extern "C" void kernel_launch(void* const* d_in, const int* in_sizes, int n_in,
                              void* d_out, int out_size) {
    const float* LL = (const float*)d_in[0];
    float* out = (float*)d_out;
    (void)in_sizes; (void)n_in; (void)out_size;

    static unsigned int *red_ptr = nullptr, *cnt_ptr = nullptr;
    if (!red_ptr) {
        cudaGetSymbolAddress((void**)&red_ptr, g_red);
        cudaGetSymbolAddress((void**)&cnt_ptr, g_count);
    }

    cudaMemsetAsync(red_ptr, 0xFF, 2 * sizeof(unsigned int));  // min sentinels
    cudaMemsetAsync(cnt_ptr, 0x00, sizeof(unsigned int));      // barrier count
    qwt_fused_kernel<<<NBLK, THREADS>>>(LL, out);
}

// round 11
// speedup vs baseline: 8.0857x; 8.0857x over previous
#include <cuda_runtime.h>
#include <math_constants.h>

// out = minmax_normalize( bicubic_up2x( LL[:, 0:8] ) )
// All other iqwt terms carry sum(gh)=sum(fl)=sum(fh)=0 (f32 residue < 3e-7);
// the surviving sg^2 scalar cancels in the min-max normalization.
//
// memset node: g_red sentinels (both 0xFFFFFFFF).
// Pass 1: upsample (discard), min/max -> 2 atomics per block.
// Pass 2: recompute (input L2-resident), fused normalize.
// TILE_J=16: 20-row slab per block (1.25x halo amplification), each thread
// covers 4 out cols x 8 out rows in each of 2 row-groups. STG.128 coalesced.

#define THREADS 256
#define TILE_J  16            // input rows per block -> 32 output rows
#define IN_ROWS 20            // 16 + 4 halo
#define SMEM_W  264           // 4 pad | 256 | 4 pad
#define N_IN    256
#define N_OUT   512
#define N_IMG   64
#define TILES_PER_IMG 16
#define GRID (N_IMG * TILES_PER_IMG)   // 1024

// bicubic a=-0.75, src = 0.5*i - 0.25
#define WE0 (-0.03515625f)
#define WE1 ( 0.26171875f)
#define WE2 ( 0.87890625f)
#define WE3 (-0.10546875f)
#define WO0 (-0.10546875f)
#define WO1 ( 0.87890625f)
#define WO2 ( 0.26171875f)
#define WO3 (-0.03515625f)

__device__ unsigned int g_red[2];   // [0]=min(enc(v)), [1]=min(enc(-v))

__device__ __forceinline__ unsigned int encf(float f) {
    unsigned int u = __float_as_uint(f);
    return (u & 0x80000000u) ? ~u : (u | 0x80000000u);
}
__device__ __forceinline__ float decf(unsigned int e) {
    unsigned int u = (e & 0x80000000u) ? (e ^ 0x80000000u) : ~e;
    return __uint_as_float(u);
}

__device__ __forceinline__ void fill_tile(float (*s)[SMEM_W],
                                          const float* __restrict__ src,
                                          int jbase, int t) {
    // 20 rows x 64 float4 = 1280 chunks, 5/thread, coalesced LDG.128+STS.128.
#pragma unroll
    for (int i = 0; i < 5; i++) {
        const int f  = t + i * THREADS;      // 0..1279
        const int rr = f >> 6;               // 0..19
        const int qc = f & 63;
        const int gr = min(max(jbase - 2 + rr, 0), N_IN - 1);
        *reinterpret_cast<float4*>(&s[rr][4 * qc + 4]) =
            *reinterpret_cast<const float4*>(src + gr * N_IN + 4 * qc);
    }
    if (t < IN_ROWS) {
        const int gr = min(max(jbase - 2 + t, 0), N_IN - 1);
        const float v = src[gr * N_IN];
        s[t][2] = v; s[t][3] = v;
    } else if (t >= 128 && t < 128 + IN_ROWS) {
        const int rr = t - 128;
        const int gr = min(max(jbase - 2 + rr, 0), N_IN - 1);
        const float v = src[gr * N_IN + (N_IN - 1)];
        s[rr][260] = v; s[rr][261] = v;
    }
}

__device__ __forceinline__ void hpass(const float (*s)[SMEM_W], int rowbase,
                                      int k, float hb[8][4]) {
#pragma unroll
    for (int r = 0; r < 8; r++) {
        const float* rp = &s[rowbase + r][2 * k + 2];
        const float2 z01 = *reinterpret_cast<const float2*>(rp);
        const float2 z23 = *reinterpret_cast<const float2*>(rp + 2);
        const float2 z45 = *reinterpret_cast<const float2*>(rp + 4);
        const float z0 = z01.x, z1 = z01.y, z2 = z23.x;
        const float z3 = z23.y, z4 = z45.x, z5 = z45.y;
        hb[r][0] = WE0 * z0 + WE1 * z1 + WE2 * z2 + WE3 * z3;
        hb[r][1] = WO0 * z1 + WO1 * z2 + WO2 * z3 + WO3 * z4;
        hb[r][2] = WE0 * z1 + WE1 * z2 + WE2 * z3 + WE3 * z4;
        hb[r][3] = WO0 * z2 + WO1 * z3 + WO2 * z4 + WO3 * z5;
    }
}

__device__ __forceinline__ void vrow(const float hb[8][4], int a, float o[4]) {
    const int ra = a >> 1;
    if ((a & 1) == 0) {
#pragma unroll
        for (int c = 0; c < 4; c++)
            o[c] = WE0 * hb[ra][c] + WE1 * hb[ra + 1][c]
                 + WE2 * hb[ra + 2][c] + WE3 * hb[ra + 3][c];
    } else {
#pragma unroll
        for (int c = 0; c < 4; c++)
            o[c] = WO0 * hb[ra + 1][c] + WO1 * hb[ra + 2][c]
                 + WO2 * hb[ra + 3][c] + WO3 * hb[ra + 4][c];
    }
}

template <bool WRITE>
__global__ __launch_bounds__(THREADS)
void qwt_up_kernel(const float* __restrict__ LL, float* __restrict__ out) {
    __shared__ __align__(16) float s[IN_ROWS][SMEM_W];

    const int t    = threadIdx.x;
    const int img  = blockIdx.x >> 4;        // 0..63
    const int tile = blockIdx.x & 15;        // 0..15
    const int b    = img >> 3;
    const int ch   = img & 7;                // lglg = LL channels 0..7
    const float* __restrict__ src = LL + (size_t)(b * 32 + ch) * (N_IN * N_IN);
    const int jbase = tile * TILE_J;

    float scale = 1.0f, bias = 0.0f;
    if (WRITE) {
        const float mn =  decf(g_red[0]);
        const float mx = -decf(g_red[1]);
        scale = 1.0f / (mx - mn);
        bias  = -mn * scale;
    }

    fill_tile(s, src, jbase, t);
    __syncthreads();

    const int k = t & 127;                   // out cols 4k..4k+3
    const int g = t >> 7;                    // group base: G = g, g+2

    float lmin =  CUDART_INF_F;
    float lmax = -CUDART_INF_F;
    const size_t obase = (size_t)img * (N_OUT * N_OUT) + 4 * k;

#pragma unroll
    for (int gg = 0; gg < 2; gg++) {
        const int G = g + 2 * gg;            // 0..3: smem rows 4G..4G+7
        float hb[8][4];
        hpass(s, 4 * G, k, hb);

        const int rbase = tile * 32 + 8 * G;
#pragma unroll
        for (int a = 0; a < 8; a++) {
            float o[4];
            vrow(hb, a, o);
            if (WRITE) {
                float4 v;
                v.x = fmaf(o[0], scale, bias); v.y = fmaf(o[1], scale, bias);
                v.z = fmaf(o[2], scale, bias); v.w = fmaf(o[3], scale, bias);
                *reinterpret_cast<float4*>(out + obase + (size_t)(rbase + a) * N_OUT) = v;
            } else {
                lmin = fminf(lmin, fminf(fminf(o[0], o[1]), fminf(o[2], o[3])));
                lmax = fmaxf(lmax, fmaxf(fmaxf(o[0], o[1]), fmaxf(o[2], o[3])));
            }
        }
    }

    if (!WRITE) {
#pragma unroll
        for (int off = 16; off > 0; off >>= 1) {
            lmin = fminf(lmin, __shfl_xor_sync(0xFFFFFFFFu, lmin, off));
            lmax = fmaxf(lmax, __shfl_xor_sync(0xFFFFFFFFu, lmax, off));
        }
        __shared__ float wmin[THREADS / 32], wmax[THREADS / 32];
        const int w = t >> 5, l = t & 31;
        if (l == 0) { wmin[w] = lmin; wmax[w] = lmax; }
        __syncthreads();
        if (t == 0) {
            float m = wmin[0], M = wmax[0];
#pragma unroll
            for (int i = 1; i < THREADS / 32; i++) {
                m = fminf(m, wmin[i]);
                M = fmaxf(M, wmax[i]);
            }
            atomicMin(&g_red[0], encf(m));
            atomicMin(&g_red[1], encf(-M));
        }
    }
}

extern "C" void kernel_launch(void* const* d_in, const int* in_sizes, int n_in,
                              void* d_out, int out_size) {
    const float* LL = (const float*)d_in[0];
    float* out = (float*)d_out;
    (void)in_sizes; (void)n_in; (void)out_size;

    static unsigned int* red_ptr = nullptr;
    if (!red_ptr) cudaGetSymbolAddress((void**)&red_ptr, g_red);

    cudaMemsetAsync(red_ptr, 0xFF, 2 * sizeof(unsigned int));
    qwt_up_kernel<false><<<GRID, THREADS>>>(LL, out);  // min/max pass
    qwt_up_kernel<true ><<<GRID, THREADS>>>(LL, out);  // normalize + write pass
}